// round 1
// baseline (speedup 1.0000x reference)
#include <cuda_runtime.h>
#include <cstdint>

#define N_ROWS 262144
#define DD 64
#define KK 1024
#define ROWS_PER_BLOCK 64
#define CHUNK 128
#define NCHUNK (KK / CHUNK)
#define THREADS 256

// dynamic smem layout (floats):
//   xs    [0,      4096)   : x tile, transposed [k][row], XOR-swizzled float4 groups
//   cs    [4096,  12288)   : code chunk, transposed [k][code], swizzled
//   a_sh  [12288, 12352)   : per-row sum(x^2)
//   b_sh  [12352, 12480)   : per-code sum(e^2)
//   cand_s[12480, 13504)   : per-(row,codegroup) best score
//   cand_i[13504, 14528)   : per-(row,codegroup) best index (int)
//   idx_f [14528, 14592)   : final per-row argmin (int)
#define SMEM_FLOATS 14592
#define SMEM_BYTES (SMEM_FLOATS * 4)

__device__ double g_loss_accum;

__device__ __forceinline__ unsigned long long pack2(float lo, float hi) {
    unsigned long long r;
    asm("mov.b64 %0, {%1, %2};" : "=l"(r) : "f"(lo), "f"(hi));
    return r;
}
__device__ __forceinline__ void unpack2(unsigned long long v, float& lo, float& hi) {
    asm("mov.b64 {%0, %1}, %2;" : "=f"(lo), "=f"(hi) : "l"(v));
}
__device__ __forceinline__ unsigned long long fma2(unsigned long long a,
                                                   unsigned long long b,
                                                   unsigned long long c) {
    unsigned long long d;
    asm("fma.rn.f32x2 %0, %1, %2, %3;" : "=l"(d) : "l"(a), "l"(b), "l"(c));
    return d;
}

__global__ void __launch_bounds__(THREADS)
vq_zero_kernel() { g_loss_accum = 0.0; }

__global__ void __launch_bounds__(THREADS)
vq_main_kernel(const float* __restrict__ x,
               const float* __restrict__ cb,
               float* __restrict__ out) {
    extern __shared__ float sm[];
    float* xs     = sm;
    float* cs     = sm + 4096;
    float* a_sh   = sm + 12288;
    float* b_sh   = sm + 12352;
    float* cand_s = sm + 12480;
    int*   cand_i = reinterpret_cast<int*>(sm + 13504);
    int*   idx_f  = reinterpret_cast<int*>(sm + 14528);

    const int t = threadIdx.x;
    const long long rowBase = (long long)blockIdx.x * ROWS_PER_BLOCK;

    // ---- load x tile: global [row][d] -> smem transposed [k][row], swizzled ----
    #pragma unroll
    for (int i = 0; i < 4; i++) {
        int f   = i * 256 + t;       // float4 id in [0,1024)
        int row = f >> 4;
        int d4  = f & 15;
        float4 v = *reinterpret_cast<const float4*>(x + (rowBase + row) * DD + d4 * 4);
        int g  = row >> 2;
        int ro = row & 3;
        int pg = (g ^ d4) & 15;      // swizzle: k>>2 == d4
        xs[(4 * d4 + 0) * 64 + pg * 4 + ro] = v.x;
        xs[(4 * d4 + 1) * 64 + pg * 4 + ro] = v.y;
        xs[(4 * d4 + 2) * 64 + pg * 4 + ro] = v.z;
        xs[(4 * d4 + 3) * 64 + pg * 4 + ro] = v.w;
    }
    __syncthreads();

    // ---- per-row a = sum(x^2), sequential fp32 (mirrors reference) ----
    if (t < 64) {
        int row = t, g = row >> 2, ro = row & 3;
        float s = 0.f;
        #pragma unroll
        for (int k = 0; k < 64; k++) {
            float v = xs[k * 64 + ((g ^ (k >> 2)) & 15) * 4 + ro];
            s = fmaf(v, v, s);
        }
        a_sh[row] = s;
    }
    __syncthreads();

    const int rg = t & 15;   // row group: rows 4*rg .. 4*rg+3
    const int cg = t >> 4;   // code group: 8 codes per chunk

    float a_reg[4];
    #pragma unroll
    for (int r = 0; r < 4; r++) a_reg[r] = a_sh[4 * rg + r];

    float best[4];
    int   bidx[4];
    #pragma unroll
    for (int r = 0; r < 4; r++) { best[r] = 3.4e38f; bidx[r] = 0; }

    for (int ch = 0; ch < NCHUNK; ch++) {
        // ---- load code chunk: global [code][d] -> smem transposed [k][code], swizzled ----
        #pragma unroll
        for (int i = 0; i < 8; i++) {
            int f  = i * 256 + t;    // float4 id in [0,2048)
            int c  = f >> 4;
            int d4 = f & 15;
            float4 v = *reinterpret_cast<const float4*>(cb + (ch * CHUNK + c) * DD + d4 * 4);
            int g  = c >> 2;
            int co = c & 3;
            int pg = (g ^ d4) & 31;
            cs[(4 * d4 + 0) * 128 + pg * 4 + co] = v.x;
            cs[(4 * d4 + 1) * 128 + pg * 4 + co] = v.y;
            cs[(4 * d4 + 2) * 128 + pg * 4 + co] = v.z;
            cs[(4 * d4 + 3) * 128 + pg * 4 + co] = v.w;
        }
        __syncthreads();

        // ---- per-code b = sum(e^2), sequential fp32 ----
        if (t < 128) {
            int c = t, g = c >> 2, co = c & 3;
            float s = 0.f;
            #pragma unroll
            for (int k = 0; k < 64; k++) {
                float v = cs[k * 128 + ((g ^ (k >> 2)) & 31) * 4 + co];
                s = fmaf(v, v, s);
            }
            b_sh[c] = s;
        }
        __syncthreads();

        // ---- main dot-product loop: 4 rows x 8 codes, packed f32x2 ----
        unsigned long long acc[4][4];
        #pragma unroll
        for (int r = 0; r < 4; r++)
            #pragma unroll
            for (int p = 0; p < 4; p++) acc[r][p] = 0ULL;

        #pragma unroll
        for (int k4 = 0; k4 < 16; k4++) {
            const int xg = ((rg ^ k4) & 15) * 4;
            const int g0 = ((2 * cg) ^ k4) & 31;
            const int g1 = ((2 * cg + 1) ^ k4) & 31;
            #pragma unroll
            for (int j = 0; j < 4; j++) {
                const int k = 4 * k4 + j;
                float4 xv = *reinterpret_cast<const float4*>(&xs[k * 64 + xg]);
                const unsigned long long* c0 =
                    reinterpret_cast<const unsigned long long*>(&cs[k * 128 + g0 * 4]);
                const unsigned long long* c1 =
                    reinterpret_cast<const unsigned long long*>(&cs[k * 128 + g1 * 4]);
                unsigned long long cA = c0[0], cB = c0[1], cC = c1[0], cD = c1[1];
                float xr[4] = {xv.x, xv.y, xv.z, xv.w};
                #pragma unroll
                for (int r = 0; r < 4; r++) {
                    unsigned long long xp = pack2(xr[r], xr[r]);
                    acc[r][0] = fma2(xp, cA, acc[r][0]);
                    acc[r][1] = fma2(xp, cB, acc[r][1]);
                    acc[r][2] = fma2(xp, cC, acc[r][2]);
                    acc[r][3] = fma2(xp, cD, acc[r][3]);
                }
            }
        }

        // ---- epilogue: scores s = (a + b) - 2*dot, running argmin (asc. index) ----
        #pragma unroll
        for (int r = 0; r < 4; r++) {
            #pragma unroll
            for (int p = 0; p < 4; p++) {
                float d0, d1;
                unpack2(acc[r][p], d0, d1);
                int   lc = 8 * cg + 2 * p;
                int   gc = ch * CHUNK + lc;
                float b0 = b_sh[lc], b1 = b_sh[lc + 1];
                float s0 = (a_reg[r] + b0) - 2.0f * d0;
                float s1 = (a_reg[r] + b1) - 2.0f * d1;
                if (s0 < best[r]) { best[r] = s0; bidx[r] = gc; }
                if (s1 < best[r]) { best[r] = s1; bidx[r] = gc + 1; }
            }
        }
        __syncthreads();   // protect cs/b_sh before next chunk fill
    }

    // ---- cross-codegroup reduction per row (tie -> lowest index, like argmin) ----
    #pragma unroll
    for (int r = 0; r < 4; r++) {
        cand_s[(4 * rg + r) * 16 + cg] = best[r];
        cand_i[(4 * rg + r) * 16 + cg] = bidx[r];
    }
    __syncthreads();
    if (t < 64) {
        float bs = 3.4e38f;
        int   bi = 0x40000000;
        #pragma unroll
        for (int g = 0; g < 16; g++) {
            float s = cand_s[t * 16 + g];
            int   i = cand_i[t * 16 + g];
            if (s < bs || (s == bs && i < bi)) { bs = s; bi = i; }
        }
        idx_f[t] = bi;
    }
    __syncthreads();

    // ---- gather + straight-through output + loss accumulation ----
    const int row   = t >> 2;
    const int dbase = (t & 3) * 16;
    const int ci    = idx_f[row];
    const float* crow = cb + (long long)ci * DD;
    const long long orow = (rowBase + row) * DD;
    const int g = row >> 2, ro = row & 3;

    double ls = 0.0;
    #pragma unroll
    for (int i4 = 0; i4 < 4; i4++) {
        int d = dbase + i4 * 4;
        float4 q = *reinterpret_cast<const float4*>(crow + d);
        float xv[4];
        #pragma unroll
        for (int j = 0; j < 4; j++) {
            int k = d + j;
            xv[j] = xs[k * 64 + ((g ^ (k >> 2)) & 15) * 4 + ro];
        }
        float d0 = q.x - xv[0], d1 = q.y - xv[1];
        float d2 = q.z - xv[2], d3 = q.w - xv[3];
        float4 o;
        o.x = xv[0] + d0;  // mirrors x + (q - x) in fp32
        o.y = xv[1] + d1;
        o.z = xv[2] + d2;
        o.w = xv[3] + d3;
        *reinterpret_cast<float4*>(out + orow + d) = o;
        ls += (double)(d0 * d0) + (double)(d1 * d1)
            + (double)(d2 * d2) + (double)(d3 * d3);
    }
    #pragma unroll
    for (int off = 16; off > 0; off >>= 1)
        ls += __shfl_down_sync(0xffffffffu, ls, off);
    if ((t & 31) == 0) atomicAdd(&g_loss_accum, ls);
}

__global__ void __launch_bounds__(32)
vq_finalize_kernel(float* __restrict__ out, int out_size) {
    if (threadIdx.x == 0 && out_size > N_ROWS * DD) {
        double m = g_loss_accum / (double)((long long)N_ROWS * DD);
        float  q = (float)m;                 // == both e_latent and q_latent
        out[N_ROWS * DD] = q + 0.25f * q;    // q_latent + COMMITMENT_COST * e_latent
    }
}

extern "C" void kernel_launch(void* const* d_in, const int* in_sizes, int n_in,
                              void* d_out, int out_size) {
    const float* x  = (const float*)d_in[0];   // [262144, 64]
    const float* cb = (const float*)d_in[1];   // [1024, 64]
    float* out = (float*)d_out;

    cudaFuncSetAttribute(vq_main_kernel,
                         cudaFuncAttributeMaxDynamicSharedMemorySize, SMEM_BYTES);

    vq_zero_kernel<<<1, THREADS>>>();
    vq_main_kernel<<<N_ROWS / ROWS_PER_BLOCK, THREADS, SMEM_BYTES>>>(x, cb, out);
    vq_finalize_kernel<<<1, 32>>>(out, out_size);
}

// round 2
// speedup vs baseline: 1.0007x; 1.0007x over previous
#include <cuda_runtime.h>
#include <cstdint>

#define N_ROWS 262144
#define DD 64
#define KK 1024
#define ROWS_PER_BLOCK 64
#define CHUNK 128
#define NCHUNK (KK / CHUNK)
#define THREADS 256

// dynamic smem layout (floats):
//   xs    [0,      4096)   : x tile, transposed [k][row], XOR-swizzled float4 groups
//   cs    [4096,  12288)   : code chunk, transposed [k][code], swizzled
//   a_sh  [12288, 12352)   : per-row sum(x^2)
//   b_sh  [12352, 12480)   : per-code sum(e^2)
//   cand_s[12480, 13504)   : per-(row,codegroup) best score
//   cand_i[13504, 14528)   : per-(row,codegroup) best index (int)
//   idx_f [14528, 14592)   : final per-row argmin (int)
#define SMEM_FLOATS 14592
#define SMEM_BYTES (SMEM_FLOATS * 4)

__device__ double g_loss_accum;

__device__ __forceinline__ unsigned long long pack2(float lo, float hi) {
    unsigned long long r;
    asm("mov.b64 %0, {%1, %2};" : "=l"(r) : "f"(lo), "f"(hi));
    return r;
}
__device__ __forceinline__ void unpack2(unsigned long long v, float& lo, float& hi) {
    asm("mov.b64 {%0, %1}, %2;" : "=f"(lo), "=f"(hi) : "l"(v));
}
__device__ __forceinline__ unsigned long long fma2(unsigned long long a,
                                                   unsigned long long b,
                                                   unsigned long long c) {
    unsigned long long d;
    asm("fma.rn.f32x2 %0, %1, %2, %3;" : "=l"(d) : "l"(a), "l"(b), "l"(c));
    return d;
}

__global__ void __launch_bounds__(THREADS)
vq_zero_kernel() { g_loss_accum = 0.0; }

__global__ void __launch_bounds__(THREADS)
vq_main_kernel(const float* __restrict__ x,
               const float* __restrict__ cb,
               float* __restrict__ out) {
    extern __shared__ float sm[];
    float* xs     = sm;
    float* cs     = sm + 4096;
    float* a_sh   = sm + 12288;
    float* b_sh   = sm + 12352;
    float* cand_s = sm + 12480;
    int*   cand_i = reinterpret_cast<int*>(sm + 13504);
    int*   idx_f  = reinterpret_cast<int*>(sm + 14528);

    const int t = threadIdx.x;
    const long long rowBase = (long long)blockIdx.x * ROWS_PER_BLOCK;

    // ---- load x tile: global [row][d] -> smem transposed [k][row], swizzled ----
    #pragma unroll
    for (int i = 0; i < 4; i++) {
        int f   = i * 256 + t;       // float4 id in [0,1024)
        int row = f >> 4;
        int d4  = f & 15;
        float4 v = *reinterpret_cast<const float4*>(x + (rowBase + row) * DD + d4 * 4);
        int g  = row >> 2;
        int ro = row & 3;
        int pg = (g ^ d4) & 15;      // swizzle: k>>2 == d4
        xs[(4 * d4 + 0) * 64 + pg * 4 + ro] = v.x;
        xs[(4 * d4 + 1) * 64 + pg * 4 + ro] = v.y;
        xs[(4 * d4 + 2) * 64 + pg * 4 + ro] = v.z;
        xs[(4 * d4 + 3) * 64 + pg * 4 + ro] = v.w;
    }
    __syncthreads();

    // ---- per-row a = sum(x^2), sequential fp32 (mirrors reference) ----
    if (t < 64) {
        int row = t, g = row >> 2, ro = row & 3;
        float s = 0.f;
        #pragma unroll
        for (int k = 0; k < 64; k++) {
            float v = xs[k * 64 + ((g ^ (k >> 2)) & 15) * 4 + ro];
            s = fmaf(v, v, s);
        }
        a_sh[row] = s;
    }
    __syncthreads();

    const int rg = t & 15;   // row group: rows 4*rg .. 4*rg+3
    const int cg = t >> 4;   // code group: 8 codes per chunk

    float a_reg[4];
    #pragma unroll
    for (int r = 0; r < 4; r++) a_reg[r] = a_sh[4 * rg + r];

    float best[4];
    int   bidx[4];
    #pragma unroll
    for (int r = 0; r < 4; r++) { best[r] = 3.4e38f; bidx[r] = 0; }

    for (int ch = 0; ch < NCHUNK; ch++) {
        // ---- load code chunk: global [code][d] -> smem transposed [k][code], swizzled ----
        #pragma unroll
        for (int i = 0; i < 8; i++) {
            int f  = i * 256 + t;    // float4 id in [0,2048)
            int c  = f >> 4;
            int d4 = f & 15;
            float4 v = *reinterpret_cast<const float4*>(cb + (ch * CHUNK + c) * DD + d4 * 4);
            int g  = c >> 2;
            int co = c & 3;
            int pg = (g ^ d4) & 31;
            cs[(4 * d4 + 0) * 128 + pg * 4 + co] = v.x;
            cs[(4 * d4 + 1) * 128 + pg * 4 + co] = v.y;
            cs[(4 * d4 + 2) * 128 + pg * 4 + co] = v.z;
            cs[(4 * d4 + 3) * 128 + pg * 4 + co] = v.w;
        }
        __syncthreads();

        // ---- per-code b = sum(e^2), sequential fp32 ----
        if (t < 128) {
            int c = t, g = c >> 2, co = c & 3;
            float s = 0.f;
            #pragma unroll
            for (int k = 0; k < 64; k++) {
                float v = cs[k * 128 + ((g ^ (k >> 2)) & 31) * 4 + co];
                s = fmaf(v, v, s);
            }
            b_sh[c] = s;
        }
        __syncthreads();

        // ---- main dot-product loop: 4 rows x 8 codes, packed f32x2 ----
        unsigned long long acc[4][4];
        #pragma unroll
        for (int r = 0; r < 4; r++)
            #pragma unroll
            for (int p = 0; p < 4; p++) acc[r][p] = 0ULL;

        #pragma unroll
        for (int k4 = 0; k4 < 16; k4++) {
            const int xg = ((rg ^ k4) & 15) * 4;
            const int g0 = ((2 * cg) ^ k4) & 31;
            const int g1 = ((2 * cg + 1) ^ k4) & 31;
            #pragma unroll
            for (int j = 0; j < 4; j++) {
                const int k = 4 * k4 + j;
                float4 xv = *reinterpret_cast<const float4*>(&xs[k * 64 + xg]);
                const unsigned long long* c0 =
                    reinterpret_cast<const unsigned long long*>(&cs[k * 128 + g0 * 4]);
                const unsigned long long* c1 =
                    reinterpret_cast<const unsigned long long*>(&cs[k * 128 + g1 * 4]);
                unsigned long long cA = c0[0], cB = c0[1], cC = c1[0], cD = c1[1];
                float xr[4] = {xv.x, xv.y, xv.z, xv.w};
                #pragma unroll
                for (int r = 0; r < 4; r++) {
                    unsigned long long xp = pack2(xr[r], xr[r]);
                    acc[r][0] = fma2(xp, cA, acc[r][0]);
                    acc[r][1] = fma2(xp, cB, acc[r][1]);
                    acc[r][2] = fma2(xp, cC, acc[r][2]);
                    acc[r][3] = fma2(xp, cD, acc[r][3]);
                }
            }
        }

        // ---- epilogue: scores s = (a + b) - 2*dot, running argmin (asc. index) ----
        #pragma unroll
        for (int r = 0; r < 4; r++) {
            #pragma unroll
            for (int p = 0; p < 4; p++) {
                float d0, d1;
                unpack2(acc[r][p], d0, d1);
                int   lc = 8 * cg + 2 * p;
                int   gc = ch * CHUNK + lc;
                float b0 = b_sh[lc], b1 = b_sh[lc + 1];
                float s0 = (a_reg[r] + b0) - 2.0f * d0;
                float s1 = (a_reg[r] + b1) - 2.0f * d1;
                if (s0 < best[r]) { best[r] = s0; bidx[r] = gc; }
                if (s1 < best[r]) { best[r] = s1; bidx[r] = gc + 1; }
            }
        }
        __syncthreads();   // protect cs/b_sh before next chunk fill
    }

    // ---- cross-codegroup reduction per row (tie -> lowest index, like argmin) ----
    #pragma unroll
    for (int r = 0; r < 4; r++) {
        cand_s[(4 * rg + r) * 16 + cg] = best[r];
        cand_i[(4 * rg + r) * 16 + cg] = bidx[r];
    }
    __syncthreads();
    if (t < 64) {
        float bs = 3.4e38f;
        int   bi = 0x40000000;
        #pragma unroll
        for (int g = 0; g < 16; g++) {
            float s = cand_s[t * 16 + g];
            int   i = cand_i[t * 16 + g];
            if (s < bs || (s == bs && i < bi)) { bs = s; bi = i; }
        }
        idx_f[t] = bi;
    }
    __syncthreads();

    // ---- gather + straight-through output + loss accumulation ----
    const int row   = t >> 2;
    const int dbase = (t & 3) * 16;
    const int ci    = idx_f[row];
    const float* crow = cb + (long long)ci * DD;
    const long long orow = (rowBase + row) * DD;
    const int g = row >> 2, ro = row & 3;

    double ls = 0.0;
    #pragma unroll
    for (int i4 = 0; i4 < 4; i4++) {
        int d = dbase + i4 * 4;
        float4 q = *reinterpret_cast<const float4*>(crow + d);
        float xv[4];
        #pragma unroll
        for (int j = 0; j < 4; j++) {
            int k = d + j;
            xv[j] = xs[k * 64 + ((g ^ (k >> 2)) & 15) * 4 + ro];
        }
        float d0 = q.x - xv[0], d1 = q.y - xv[1];
        float d2 = q.z - xv[2], d3 = q.w - xv[3];
        float4 o;
        o.x = xv[0] + d0;  // mirrors x + (q - x) in fp32
        o.y = xv[1] + d1;
        o.z = xv[2] + d2;
        o.w = xv[3] + d3;
        *reinterpret_cast<float4*>(out + orow + d) = o;
        ls += (double)(d0 * d0) + (double)(d1 * d1)
            + (double)(d2 * d2) + (double)(d3 * d3);
    }
    #pragma unroll
    for (int off = 16; off > 0; off >>= 1)
        ls += __shfl_down_sync(0xffffffffu, ls, off);
    if ((t & 31) == 0) atomicAdd(&g_loss_accum, ls);
}

__global__ void __launch_bounds__(32)
vq_finalize_kernel(float* __restrict__ out, int out_size) {
    if (threadIdx.x == 0 && out_size > N_ROWS * DD) {
        double m = g_loss_accum / (double)((long long)N_ROWS * DD);
        float  q = (float)m;                 // == both e_latent and q_latent
        out[N_ROWS * DD] = q + 0.25f * q;    // q_latent + COMMITMENT_COST * e_latent
    }
}

extern "C" void kernel_launch(void* const* d_in, const int* in_sizes, int n_in,
                              void* d_out, int out_size) {
    const float* x  = (const float*)d_in[0];   // [262144, 64]
    const float* cb = (const float*)d_in[1];   // [1024, 64]
    float* out = (float*)d_out;

    cudaFuncSetAttribute(vq_main_kernel,
                         cudaFuncAttributeMaxDynamicSharedMemorySize, SMEM_BYTES);

    vq_zero_kernel<<<1, THREADS>>>();
    vq_main_kernel<<<N_ROWS / ROWS_PER_BLOCK, THREADS, SMEM_BYTES>>>(x, cb, out);
    vq_finalize_kernel<<<1, 32>>>(out, out_size);
}